// round 1
// baseline (speedup 1.0000x reference)
#include <cuda_runtime.h>
#include <cuda_bf16.h>
#include <math.h>

// ----------------------------------------------------------------------------
// Problem constants (this instance): M=D=10000, FG=FD=256, H1=2, K=64, E=320000
// ----------------------------------------------------------------------------
#define MAXN 10000
#define MAXE 320000
#define CDIM 256   // per-head channel dim (FG == FD == 256)

// ------------------------- device scratch (no mallocs) ----------------------
__device__ float g_bufA[MAXN * 512];     // xp / gemm outputs   (20.5 MB)
__device__ float g_bufB[MAXN * 512];     // layer outputs       (20.5 MB)
__device__ float g_bufC[MAXN * 256];     // 2nd-layer output    (10.2 MB)
__device__ float g_als[MAXN * 2];
__device__ float g_ald[MAXN * 2];
__device__ float g_elog[MAXE * 2];
__device__ int   g_deg[MAXN + 1];
__device__ int   g_off[MAXN + 1];
__device__ int   g_cur[MAXN];
__device__ int   g_sorted[MAXE];
__device__ float g_xfin[MAXN * 64];
__device__ float g_yfin[MAXN * 64];
__device__ float g_yT[64 * MAXN];

// ------------------------------ tiny kernels --------------------------------
__global__ void zero_int_kernel(int* p, int n) {
    int i = blockIdx.x * blockDim.x + threadIdx.x;
    if (i < n) p[i] = 0;
}

__global__ void hist_kernel(const int* __restrict__ dst, int E, int* __restrict__ deg) {
    int e = blockIdx.x * blockDim.x + threadIdx.x;
    if (e < E) atomicAdd(&deg[dst[e]], 1);
}

// single-block exclusive scan over n<=10240 degrees -> offsets[0..n]
__global__ void scan_kernel(const int* __restrict__ deg, int* __restrict__ off, int n) {
    const int T = 1024;
    int t = threadIdx.x;
    int chunk = (n + T - 1) / T;
    int b = t * chunk;
    int e2 = b + chunk; if (e2 > n) e2 = n;
    int s = 0;
    for (int i = b; i < e2; i++) s += deg[i];
    __shared__ int sh[T];
    sh[t] = s;
    __syncthreads();
    for (int d2 = 1; d2 < T; d2 <<= 1) {
        int v = (t >= d2) ? sh[t - d2] : 0;
        __syncthreads();
        sh[t] += v;
        __syncthreads();
    }
    int run = (t == 0) ? 0 : sh[t - 1];
    for (int i = b; i < e2; i++) { off[i] = run; run += deg[i]; }
    if (t == 0) off[n] = sh[T - 1];
}

__global__ void scatter_kernel(const int* __restrict__ dst, int E,
                               const int* __restrict__ off, int* __restrict__ cur,
                               int* __restrict__ sorted) {
    int e = blockIdx.x * blockDim.x + threadIdx.x;
    if (e < E) {
        int d = dst[e];
        int p = atomicAdd(&cur[d], 1);
        sorted[off[d] + p] = e;
    }
}

// ------------------------------- SGEMM --------------------------------------
// C[M,N] = A[M,K] @ B[K,N] (+bias) (optional relu). Row-major. K % BK == 0.
template <int BM, int BN, int BK, int TM, int TN>
__global__ __launch_bounds__((BM / TM) * (BN / TN))
void sgemm_kernel(int M, int N, int K,
                  const float* __restrict__ A, const float* __restrict__ B,
                  const float* __restrict__ bias, float* __restrict__ C, int doRelu) {
    constexpr int THREADS = (BM / TM) * (BN / TN);
    __shared__ float As[BK][BM];
    __shared__ float Bs[BK][BN];
    int tid = threadIdx.x;
    int blockRow = blockIdx.y * BM;
    int blockCol = blockIdx.x * BN;
    int trow = tid / (BN / TN);
    int tcol = tid % (BN / TN);
    float acc[TM][TN];
#pragma unroll
    for (int i = 0; i < TM; i++)
#pragma unroll
        for (int j = 0; j < TN; j++) acc[i][j] = 0.f;

    for (int k0 = 0; k0 < K; k0 += BK) {
#pragma unroll 4
        for (int i = tid; i < BM * BK; i += THREADS) {
            int m = i / BK, kk = i % BK;
            int gm = blockRow + m;
            As[kk][m] = (gm < M) ? A[(size_t)gm * K + k0 + kk] : 0.f;
        }
#pragma unroll 4
        for (int i = tid; i < BK * BN; i += THREADS) {
            int kk = i / BN, nn = i % BN;
            int gn = blockCol + nn;
            Bs[kk][nn] = (gn < N) ? B[(size_t)(k0 + kk) * N + gn] : 0.f;
        }
        __syncthreads();
#pragma unroll
        for (int kk = 0; kk < BK; kk++) {
            float ra[TM], rb[TN];
#pragma unroll
            for (int i = 0; i < TM; i++) ra[i] = As[kk][trow * TM + i];
#pragma unroll
            for (int j = 0; j < TN; j++) rb[j] = Bs[kk][tcol * TN + j];
#pragma unroll
            for (int i = 0; i < TM; i++)
#pragma unroll
                for (int j = 0; j < TN; j++) acc[i][j] += ra[i] * rb[j];
        }
        __syncthreads();
    }
#pragma unroll
    for (int i = 0; i < TM; i++) {
        int gm = blockRow + trow * TM + i;
        if (gm >= M) continue;
#pragma unroll
        for (int j = 0; j < TN; j++) {
            int gn = blockCol + tcol * TN + j;
            if (gn >= N) continue;
            float v = acc[i][j] + (bias ? bias[gn] : 0.f);
            if (doRelu) v = fmaxf(v, 0.f);
            C[(size_t)gm * N + gn] = v;
        }
    }
}

// --------------------------- GAT-specific kernels ---------------------------
// al_s[n,h] = sum_c xp[n,h,c]*a_src[h,c]; al_d analogous. blockDim == 256 == C.
__global__ void compute_al(const float* __restrict__ xp,
                           const float* __restrict__ asrc, const float* __restrict__ adst,
                           float* __restrict__ als, float* __restrict__ ald, int H) {
    int n = blockIdx.x, tid = threadIdx.x;
    int HC = H * CDIM;
    __shared__ float sh1[8], sh2[8];
    for (int h = 0; h < H; h++) {
        float v = xp[(size_t)n * HC + h * CDIM + tid];
        float s1 = v * asrc[h * CDIM + tid];
        float s2 = v * adst[h * CDIM + tid];
#pragma unroll
        for (int o = 16; o > 0; o >>= 1) {
            s1 += __shfl_down_sync(0xffffffffu, s1, o);
            s2 += __shfl_down_sync(0xffffffffu, s2, o);
        }
        if ((tid & 31) == 0) { sh1[tid >> 5] = s1; sh2[tid >> 5] = s2; }
        __syncthreads();
        if (tid < 8) {
            s1 = sh1[tid]; s2 = sh2[tid];
#pragma unroll
            for (int o = 4; o > 0; o >>= 1) {
                s1 += __shfl_down_sync(0xffu, s1, o);
                s2 += __shfl_down_sync(0xffu, s2, o);
            }
            if (tid == 0) { als[n * H + h] = s1; ald[n * H + h] = s2; }
        }
        __syncthreads();
    }
}

__global__ void edge_logits(const int* __restrict__ src, const int* __restrict__ dst,
                            const float* __restrict__ als, const float* __restrict__ ald,
                            float* __restrict__ elog, int E, int H) {
    int e = blockIdx.x * blockDim.x + threadIdx.x;
    if (e >= E) return;
    int s = src[e], d = dst[e];
    for (int h = 0; h < H; h++) {
        float v = als[s * H + h] + ald[d * H + h];
        elog[(size_t)e * H + h] = v > 0.f ? v : 0.2f * v;
    }
}

// One CTA per destination node; 256 threads == channel dim.
// Segmented softmax (max, sum-exp) + alpha-weighted gather-aggregate, +bias, relu.
__global__ void gat_aggregate(const float* __restrict__ xp, const float* __restrict__ elog,
                              const int* __restrict__ src, const int* __restrict__ sorted,
                              const int* __restrict__ off, const float* __restrict__ bias,
                              float* __restrict__ out, int H) {
    int d = blockIdx.x, tid = threadIdx.x;
    int beg = off[d];
    int deg = off[d + 1] - beg;
    int HC = H * CDIM;
    __shared__ float sh[8];
    __shared__ float s_bcast;
    __shared__ float s_alpha[256];
    __shared__ int   s_row[256];

    for (int h = 0; h < H; h++) {
        // segment max
        float mx = -1e30f;
        for (int i = tid; i < deg; i += 256) {
            int e = sorted[beg + i];
            mx = fmaxf(mx, elog[(size_t)e * H + h]);
        }
#pragma unroll
        for (int o = 16; o > 0; o >>= 1) mx = fmaxf(mx, __shfl_down_sync(0xffffffffu, mx, o));
        if ((tid & 31) == 0) sh[tid >> 5] = mx;
        __syncthreads();
        if (tid < 8) {
            mx = sh[tid];
#pragma unroll
            for (int o = 4; o > 0; o >>= 1) mx = fmaxf(mx, __shfl_down_sync(0xffu, mx, o));
            if (tid == 0) s_bcast = mx;
        }
        __syncthreads();
        float gmax = s_bcast;

        // segment sum of exp
        float sm = 0.f;
        for (int i = tid; i < deg; i += 256) {
            int e = sorted[beg + i];
            sm += __expf(elog[(size_t)e * H + h] - gmax);
        }
#pragma unroll
        for (int o = 16; o > 0; o >>= 1) sm += __shfl_down_sync(0xffffffffu, sm, o);
        if ((tid & 31) == 0) sh[tid >> 5] = sm;
        __syncthreads();
        if (tid < 8) {
            sm = sh[tid];
#pragma unroll
            for (int o = 4; o > 0; o >>= 1) sm += __shfl_down_sync(0xffu, sm, o);
            if (tid == 0) s_bcast = sm;
        }
        __syncthreads();
        float inv = 1.f / (s_bcast + 1e-16f);

        // alpha-weighted aggregation of xp[src] rows, chunked through shared
        float acc = 0.f;
        for (int base = 0; base < deg; base += 256) {
            __syncthreads();
            int i = base + tid;
            if (i < deg) {
                int e = sorted[beg + i];
                s_alpha[tid] = __expf(elog[(size_t)e * H + h] - gmax) * inv;
                s_row[tid]   = src[e];
            }
            __syncthreads();
            int lim = deg - base; if (lim > 256) lim = 256;
            for (int j = 0; j < lim; j++) {
                acc += s_alpha[j] * xp[(size_t)s_row[j] * HC + h * CDIM + tid];
            }
        }
        out[(size_t)d * HC + h * CDIM + tid] = fmaxf(acc + bias[h * CDIM + tid], 0.f);
        __syncthreads();
    }
}

// in: [n,64] row-major -> out: [64,n]
__global__ void transpose_k64(const float* __restrict__ in, float* __restrict__ out, int n) {
    __shared__ float tile[32][33];
    int bx = blockIdx.x * 32;   // row block (n dim)
    int by = blockIdx.y * 32;   // col block (64 dim): 0 or 32
    int x = threadIdx.x, y = threadIdx.y;
    for (int i = y; i < 32; i += 8) {
        int r = bx + i, c = by + x;
        tile[i][x] = (r < n) ? in[(size_t)r * 64 + c] : 0.f;
    }
    __syncthreads();
    for (int i = y; i < 32; i += 8) {
        int c = by + i, r = bx + x;
        if (r < n) out[(size_t)c * n + r] = tile[x][i];
    }
}

// --------------------------------- host -------------------------------------
static void run_sgemm(const float* A, const float* B, const float* bias, float* C,
                      int M, int N, int K, bool relu) {
    dim3 grid((N + 63) / 64, (M + 127) / 128);
    sgemm_kernel<128, 64, 16, 8, 4><<<grid, 256>>>(M, N, K, A, B, bias, C, relu ? 1 : 0);
}

static void run_tower(const float* x, int N, int E, const int* src, const int* dst,
                      const float* W1, const float* a1s, const float* a1d, const float* b1,
                      const float* W2, const float* a2s, const float* a2d, const float* b2,
                      const float* lw1, const float* lb1, const float* lw2, const float* lb2,
                      const float* lw3, const float* lb3, float* xfin,
                      float* bufA, float* bufB, float* bufC, float* als, float* ald,
                      float* elog, int* deg, int* off, int* cur, int* sorted) {
    // counting-sort edges by destination
    zero_int_kernel<<<(N + 256) / 256, 256>>>(deg, N + 1);
    zero_int_kernel<<<(N + 255) / 256, 256>>>(cur, N);
    hist_kernel<<<(E + 255) / 256, 256>>>(dst, E, deg);
    scan_kernel<<<1, 1024>>>(deg, off, N);
    scatter_kernel<<<(E + 255) / 256, 256>>>(dst, E, off, cur, sorted);

    // GAT layer 1 (H=2, concat -> 512)
    run_sgemm(x, W1, nullptr, bufA, N, 512, 256, false);
    compute_al<<<N, 256>>>(bufA, a1s, a1d, als, ald, 2);
    edge_logits<<<(E + 255) / 256, 256>>>(src, dst, als, ald, elog, E, 2);
    gat_aggregate<<<N, 256>>>(bufA, elog, src, sorted, off, b1, bufB, 2);

    // GAT layer 2 (H=1 -> 256)
    run_sgemm(bufB, W2, nullptr, bufA, N, 256, 512, false);
    compute_al<<<N, 256>>>(bufA, a2s, a2d, als, ald, 1);
    edge_logits<<<(E + 255) / 256, 256>>>(src, dst, als, ald, elog, E, 1);
    gat_aggregate<<<N, 256>>>(bufA, elog, src, sorted, off, b2, bufC, 1);

    // MLP head: 256->256->128->64, relu each
    run_sgemm(bufC, lw1, lb1, bufA, N, 256, 256, true);
    run_sgemm(bufA, lw2, lb2, bufB, N, 128, 256, true);
    run_sgemm(bufB, lw3, lb3, xfin, N, 64, 128, true);
}

extern "C" void kernel_launch(void* const* d_in, const int* in_sizes, int n_in,
                              void* d_out, int out_size) {
    const float* x_m  = (const float*)d_in[0];
    const float* x_d  = (const float*)d_in[1];
    const int*   eix  = (const int*)d_in[2];
    const int*   eiy  = (const int*)d_in[3];
    const float* Wx1 = (const float*)d_in[4];
    const float* ax1s = (const float*)d_in[5];
    const float* ax1d = (const float*)d_in[6];
    const float* bx1 = (const float*)d_in[7];
    const float* Wx2 = (const float*)d_in[8];
    const float* ax2s = (const float*)d_in[9];
    const float* ax2d = (const float*)d_in[10];
    const float* bx2 = (const float*)d_in[11];
    const float* Wy1 = (const float*)d_in[12];
    const float* ay1s = (const float*)d_in[13];
    const float* ay1d = (const float*)d_in[14];
    const float* by1 = (const float*)d_in[15];
    const float* Wy2 = (const float*)d_in[16];
    const float* ay2s = (const float*)d_in[17];
    const float* ay2d = (const float*)d_in[18];
    const float* by2 = (const float*)d_in[19];
    const float* lwx1 = (const float*)d_in[20];
    const float* lbx1 = (const float*)d_in[21];
    const float* lwx2 = (const float*)d_in[22];
    const float* lbx2 = (const float*)d_in[23];
    const float* lwx3 = (const float*)d_in[24];
    const float* lbx3 = (const float*)d_in[25];
    const float* lwy1 = (const float*)d_in[26];
    const float* lby1 = (const float*)d_in[27];
    const float* lwy2 = (const float*)d_in[28];
    const float* lby2 = (const float*)d_in[29];
    const float* lwy3 = (const float*)d_in[30];
    const float* lby3 = (const float*)d_in[31];

    int M  = in_sizes[0] / 256;
    int D  = in_sizes[1] / 256;
    int EX = in_sizes[2] / 2;
    int EY = in_sizes[3] / 2;

    float *bufA, *bufB, *bufC, *als, *ald, *elog, *xfin, *yfin, *yT;
    int *deg, *off, *cur, *sorted;
    cudaGetSymbolAddress((void**)&bufA, g_bufA);
    cudaGetSymbolAddress((void**)&bufB, g_bufB);
    cudaGetSymbolAddress((void**)&bufC, g_bufC);
    cudaGetSymbolAddress((void**)&als, g_als);
    cudaGetSymbolAddress((void**)&ald, g_ald);
    cudaGetSymbolAddress((void**)&elog, g_elog);
    cudaGetSymbolAddress((void**)&deg, g_deg);
    cudaGetSymbolAddress((void**)&off, g_off);
    cudaGetSymbolAddress((void**)&cur, g_cur);
    cudaGetSymbolAddress((void**)&sorted, g_sorted);
    cudaGetSymbolAddress((void**)&xfin, g_xfin);
    cudaGetSymbolAddress((void**)&yfin, g_yfin);
    cudaGetSymbolAddress((void**)&yT, g_yT);

    // X tower
    run_tower(x_m, M, EX, eix, eix + EX,
              Wx1, ax1s, ax1d, bx1, Wx2, ax2s, ax2d, bx2,
              lwx1, lbx1, lwx2, lbx2, lwx3, lbx3, xfin,
              bufA, bufB, bufC, als, ald, elog, deg, off, cur, sorted);
    // Y tower
    run_tower(x_d, D, EY, eiy, eiy + EY,
              Wy1, ay1s, ay1d, by1, Wy2, ay2s, ay2d, by2,
              lwy1, lby1, lwy2, lby2, lwy3, lby3, yfin,
              bufA, bufB, bufC, als, ald, elog, deg, off, cur, sorted);

    // out = xfin @ yfin^T  -> materialize yT then big SGEMM
    transpose_k64<<<dim3((D + 31) / 32, 2), dim3(32, 8)>>>(yfin, yT, D);
    dim3 gridF((D + 127) / 128, (M + 127) / 128);
    sgemm_kernel<128, 128, 16, 8, 8><<<gridF, 256>>>(M, D, 64, xfin, yT, nullptr,
                                                     (float*)d_out, 0);
}

// round 3
// speedup vs baseline: 1.3820x; 1.3820x over previous
#include <cuda_runtime.h>
#include <cuda_bf16.h>
#include <math.h>
#include <stdint.h>

// ----------------------------------------------------------------------------
// Problem constants (this instance): M=D=10000, FG=FD=256, H1=2, K=64, E=320000
// ----------------------------------------------------------------------------
#define MAXN 10000
#define MAXE 320000
#define CDIM 256   // per-head channel dim (FG == FD == 256)

// ------------------------- device scratch (no mallocs) ----------------------
__device__ float g_bufA[MAXN * 512];     // xp / gemm outputs   (20.5 MB)
__device__ float g_bufB[MAXN * 512];     // layer outputs       (20.5 MB)
__device__ float g_bufC[MAXN * 256];     // 2nd-layer output    (10.2 MB)
__device__ float g_als[MAXN * 2];
__device__ float g_ald[MAXN * 2];
__device__ float g_elog[MAXE * 2];
__device__ int   g_deg[MAXN + 1];
__device__ int   g_off[MAXN + 1];
__device__ int   g_cur[MAXN];
__device__ int   g_sorted[MAXE];
__device__ float g_xfin[MAXN * 64];
__device__ float g_yfin[MAXN * 64];
__device__ float g_wT[512 * 256];        // transposed-weight scratch (max 512x256)

// ------------------------------ tiny kernels --------------------------------
__global__ void zero_int_kernel(int* p, int n) {
    int i = blockIdx.x * blockDim.x + threadIdx.x;
    if (i < n) p[i] = 0;
}

__global__ void hist_kernel(const int* __restrict__ dst, int E, int* __restrict__ deg) {
    int e = blockIdx.x * blockDim.x + threadIdx.x;
    if (e < E) atomicAdd(&deg[dst[e]], 1);
}

__global__ void scan_kernel(const int* __restrict__ deg, int* __restrict__ off, int n) {
    const int T = 1024;
    int t = threadIdx.x;
    int chunk = (n + T - 1) / T;
    int b = t * chunk;
    int e2 = b + chunk; if (e2 > n) e2 = n;
    int s = 0;
    for (int i = b; i < e2; i++) s += deg[i];
    __shared__ int sh[T];
    sh[t] = s;
    __syncthreads();
    for (int d2 = 1; d2 < T; d2 <<= 1) {
        int v = (t >= d2) ? sh[t - d2] : 0;
        __syncthreads();
        sh[t] += v;
        __syncthreads();
    }
    int run = (t == 0) ? 0 : sh[t - 1];
    for (int i = b; i < e2; i++) { off[i] = run; run += deg[i]; }
    if (t == 0) off[n] = sh[T - 1];
}

__global__ void scatter_kernel(const int* __restrict__ dst, int E,
                               const int* __restrict__ off, int* __restrict__ cur,
                               int* __restrict__ sorted) {
    int e = blockIdx.x * blockDim.x + threadIdx.x;
    if (e < E) {
        int d = dst[e];
        int p = atomicAdd(&cur[d], 1);
        sorted[off[d] + p] = e;
    }
}

// in [R, C] -> out [C, R]
__global__ void transpose_kernel(const float* __restrict__ in, float* __restrict__ out,
                                 int R, int C) {
    __shared__ float t[32][33];
    int c0 = blockIdx.x * 32, r0 = blockIdx.y * 32;
    int x = threadIdx.x, y = threadIdx.y;
    for (int i = y; i < 32; i += 8) {
        int r = r0 + i, c = c0 + x;
        if (r < R && c < C) t[i][x] = in[(size_t)r * C + c];
    }
    __syncthreads();
    for (int i = y; i < 32; i += 8) {
        int c = c0 + i, r = r0 + x;
        if (r < R && c < C) out[(size_t)c * R + r] = t[x][i];
    }
}

// ------------------------ tf32x3 GEMM via mma.sync --------------------------
// C[M,N] = A[M,K] @ BT[N,K]^T (+bias, +relu).
// hi/lo tf32 split; 3 mma terms (hi*hi + lo*hi + hi*lo).
// CTA 128x128, 8 warps of 32x64, BK=16, K % 16 == 0.
#define BM 128
#define BN 128
#define BK 16
#define PADK 20

__device__ __forceinline__ float tf32_rn(float a) {
    uint32_t u;
    asm("cvt.rna.tf32.f32 %0, %1;" : "=r"(u) : "f"(a));
    return __uint_as_float(u);
}

__device__ __forceinline__ void mma_m16n8k8(float* c, const uint32_t* a,
                                            const uint32_t* b) {
    asm volatile(
        "mma.sync.aligned.m16n8k8.row.col.f32.tf32.tf32.f32 "
        "{%0,%1,%2,%3}, {%4,%5,%6,%7}, {%8,%9}, {%0,%1,%2,%3};"
        : "+f"(c[0]), "+f"(c[1]), "+f"(c[2]), "+f"(c[3])
        : "r"(a[0]), "r"(a[1]), "r"(a[2]), "r"(a[3]), "r"(b[0]), "r"(b[1]));
}

__global__ __launch_bounds__(256)
void mma_gemm_kernel(int M, int N, int K,
                     const float* __restrict__ A,    // [M, K]
                     const float* __restrict__ BT,   // [N, K]
                     const float* __restrict__ bias, // [N] or null
                     float* __restrict__ C, int doRelu) {
    __shared__ float As_hi[BM][PADK];
    __shared__ float As_lo[BM][PADK];
    __shared__ float Bs_hi[BN][PADK];
    __shared__ float Bs_lo[BN][PADK];

    int tid = threadIdx.x, lane = tid & 31, wid = tid >> 5;
    int mBase = blockIdx.y * BM, nBase = blockIdx.x * BN;
    int wm = (wid & 3) * 32;   // warp m-offset within tile
    int wn = (wid >> 2) * 64;  // warp n-offset within tile

    float acc[2][8][4];
#pragma unroll
    for (int i = 0; i < 2; i++)
#pragma unroll
        for (int j = 0; j < 8; j++)
#pragma unroll
            for (int l = 0; l < 4; l++) acc[i][j][l] = 0.f;

    // loader mapping: 512 float4 per operand per chunk; 2 per thread.
    int aRow[2], aKq[2];
#pragma unroll
    for (int it = 0; it < 2; it++) {
        int idx = tid + it * 256;
        aRow[it] = idx >> 2;
        aKq[it] = idx & 3;
    }

    int KC = K >> 4;
    float4 pa[2], pb[2];

    // prefetch chunk 0
#pragma unroll
    for (int it = 0; it < 2; it++) {
        int gm = mBase + aRow[it];
        pa[it] = (gm < M) ? *(const float4*)&A[(size_t)gm * K + aKq[it] * 4]
                          : make_float4(0.f, 0.f, 0.f, 0.f);
        int gn = nBase + aRow[it];
        pb[it] = (gn < N) ? *(const float4*)&BT[(size_t)gn * K + aKq[it] * 4]
                          : make_float4(0.f, 0.f, 0.f, 0.f);
    }
    // convert + store chunk 0
#pragma unroll
    for (int it = 0; it < 2; it++) {
        float4 v = pa[it], h, l;
        h.x = tf32_rn(v.x); l.x = tf32_rn(v.x - h.x);
        h.y = tf32_rn(v.y); l.y = tf32_rn(v.y - h.y);
        h.z = tf32_rn(v.z); l.z = tf32_rn(v.z - h.z);
        h.w = tf32_rn(v.w); l.w = tf32_rn(v.w - h.w);
        *(float4*)&As_hi[aRow[it]][aKq[it] * 4] = h;
        *(float4*)&As_lo[aRow[it]][aKq[it] * 4] = l;
        v = pb[it];
        h.x = tf32_rn(v.x); l.x = tf32_rn(v.x - h.x);
        h.y = tf32_rn(v.y); l.y = tf32_rn(v.y - h.y);
        h.z = tf32_rn(v.z); l.z = tf32_rn(v.z - h.z);
        h.w = tf32_rn(v.w); l.w = tf32_rn(v.w - h.w);
        *(float4*)&Bs_hi[aRow[it]][aKq[it] * 4] = h;
        *(float4*)&Bs_lo[aRow[it]][aKq[it] * 4] = l;
    }
    __syncthreads();

    for (int ch = 0; ch < KC; ch++) {
        // prefetch next chunk into registers (overlaps with mma below)
        if (ch + 1 < KC) {
            int k0 = (ch + 1) << 4;
#pragma unroll
            for (int it = 0; it < 2; it++) {
                int gm = mBase + aRow[it];
                pa[it] = (gm < M)
                    ? *(const float4*)&A[(size_t)gm * K + k0 + aKq[it] * 4]
                    : make_float4(0.f, 0.f, 0.f, 0.f);
                int gn = nBase + aRow[it];
                pb[it] = (gn < N)
                    ? *(const float4*)&BT[(size_t)gn * K + k0 + aKq[it] * 4]
                    : make_float4(0.f, 0.f, 0.f, 0.f);
            }
        }

        // compute on current SMEM chunk: 2 ksteps of k=8
#pragma unroll
        for (int ks = 0; ks < 2; ks++) {
            int kk = ks * 8 + (lane & 3);
            int ar = wm + (lane >> 2);
            uint32_t ah[2][4], al[2][4];
#pragma unroll
            for (int mt = 0; mt < 2; mt++) {
                int r = ar + mt * 16;
                ah[mt][0] = __float_as_uint(As_hi[r][kk]);
                ah[mt][1] = __float_as_uint(As_hi[r + 8][kk]);
                ah[mt][2] = __float_as_uint(As_hi[r][kk + 4]);
                ah[mt][3] = __float_as_uint(As_hi[r + 8][kk + 4]);
                al[mt][0] = __float_as_uint(As_lo[r][kk]);
                al[mt][1] = __float_as_uint(As_lo[r + 8][kk]);
                al[mt][2] = __float_as_uint(As_lo[r][kk + 4]);
                al[mt][3] = __float_as_uint(As_lo[r + 8][kk + 4]);
            }
            int bk = ks * 8 + (lane & 3);
#pragma unroll
            for (int nt = 0; nt < 8; nt++) {
                int bn = wn + nt * 8 + (lane >> 2);
                uint32_t bh[2], bl[2];
                bh[0] = __float_as_uint(Bs_hi[bn][bk]);
                bh[1] = __float_as_uint(Bs_hi[bn][bk + 4]);
                bl[0] = __float_as_uint(Bs_lo[bn][bk]);
                bl[1] = __float_as_uint(Bs_lo[bn][bk + 4]);
#pragma unroll
                for (int mt = 0; mt < 2; mt++) {
                    mma_m16n8k8(acc[mt][nt], ah[mt], bh);
                    mma_m16n8k8(acc[mt][nt], al[mt], bh);
                    mma_m16n8k8(acc[mt][nt], ah[mt], bl);
                }
            }
        }
        __syncthreads();

        // store prefetched chunk into SMEM
        if (ch + 1 < KC) {
#pragma unroll
            for (int it = 0; it < 2; it++) {
                float4 v = pa[it], h, l;
                h.x = tf32_rn(v.x); l.x = tf32_rn(v.x - h.x);
                h.y = tf32_rn(v.y); l.y = tf32_rn(v.y - h.y);
                h.z = tf32_rn(v.z); l.z = tf32_rn(v.z - h.z);
                h.w = tf32_rn(v.w); l.w = tf32_rn(v.w - h.w);
                *(float4*)&As_hi[aRow[it]][aKq[it] * 4] = h;
                *(float4*)&As_lo[aRow[it]][aKq[it] * 4] = l;
                v = pb[it];
                h.x = tf32_rn(v.x); l.x = tf32_rn(v.x - h.x);
                h.y = tf32_rn(v.y); l.y = tf32_rn(v.y - h.y);
                h.z = tf32_rn(v.z); l.z = tf32_rn(v.z - h.z);
                h.w = tf32_rn(v.w); l.w = tf32_rn(v.w - h.w);
                *(float4*)&Bs_hi[aRow[it]][aKq[it] * 4] = h;
                *(float4*)&Bs_lo[aRow[it]][aKq[it] * 4] = l;
            }
            __syncthreads();
        }
    }

    // epilogue
#pragma unroll
    for (int mt = 0; mt < 2; mt++) {
        int r0 = mBase + wm + mt * 16 + (lane >> 2);
        int r1 = r0 + 8;
#pragma unroll
        for (int nt = 0; nt < 8; nt++) {
            int c = nBase + wn + nt * 8 + (lane & 3) * 2;
            if (c >= N) continue;
            float b0 = bias ? bias[c] : 0.f;
            float b1 = bias ? bias[c + 1] : 0.f;
            if (r0 < M) {
                float v0 = acc[mt][nt][0] + b0;
                float v1 = acc[mt][nt][1] + b1;
                if (doRelu) { v0 = fmaxf(v0, 0.f); v1 = fmaxf(v1, 0.f); }
                float2 w = make_float2(v0, v1);
                *(float2*)&C[(size_t)r0 * N + c] = w;
            }
            if (r1 < M) {
                float v2 = acc[mt][nt][2] + b0;
                float v3 = acc[mt][nt][3] + b1;
                if (doRelu) { v2 = fmaxf(v2, 0.f); v3 = fmaxf(v3, 0.f); }
                float2 w = make_float2(v2, v3);
                *(float2*)&C[(size_t)r1 * N + c] = w;
            }
        }
    }
}

// --------------------------- GAT-specific kernels ---------------------------
__global__ void compute_al(const float* __restrict__ xp,
                           const float* __restrict__ asrc, const float* __restrict__ adst,
                           float* __restrict__ als, float* __restrict__ ald, int H) {
    int n = blockIdx.x, tid = threadIdx.x;
    int HC = H * CDIM;
    __shared__ float sh1[8], sh2[8];
    for (int h = 0; h < H; h++) {
        float v = xp[(size_t)n * HC + h * CDIM + tid];
        float s1 = v * asrc[h * CDIM + tid];
        float s2 = v * adst[h * CDIM + tid];
#pragma unroll
        for (int o = 16; o > 0; o >>= 1) {
            s1 += __shfl_down_sync(0xffffffffu, s1, o);
            s2 += __shfl_down_sync(0xffffffffu, s2, o);
        }
        if ((tid & 31) == 0) { sh1[tid >> 5] = s1; sh2[tid >> 5] = s2; }
        __syncthreads();
        if (tid < 8) {
            s1 = sh1[tid]; s2 = sh2[tid];
#pragma unroll
            for (int o = 4; o > 0; o >>= 1) {
                s1 += __shfl_down_sync(0xffu, s1, o);
                s2 += __shfl_down_sync(0xffu, s2, o);
            }
            if (tid == 0) { als[n * H + h] = s1; ald[n * H + h] = s2; }
        }
        __syncthreads();
    }
}

__global__ void edge_logits(const int* __restrict__ src, const int* __restrict__ dst,
                            const float* __restrict__ als, const float* __restrict__ ald,
                            float* __restrict__ elog, int E, int H) {
    int e = blockIdx.x * blockDim.x + threadIdx.x;
    if (e >= E) return;
    int s = src[e], d = dst[e];
    for (int h = 0; h < H; h++) {
        float v = als[s * H + h] + ald[d * H + h];
        elog[(size_t)e * H + h] = v > 0.f ? v : 0.2f * v;
    }
}

__global__ void gat_aggregate(const float* __restrict__ xp, const float* __restrict__ elog,
                              const int* __restrict__ src, const int* __restrict__ sorted,
                              const int* __restrict__ off, const float* __restrict__ bias,
                              float* __restrict__ out, int H) {
    int d = blockIdx.x, tid = threadIdx.x;
    int beg = off[d];
    int deg = off[d + 1] - beg;
    int HC = H * CDIM;
    __shared__ float sh[8];
    __shared__ float s_bcast;
    __shared__ float s_alpha[256];
    __shared__ int   s_row[256];

    for (int h = 0; h < H; h++) {
        float mx = -1e30f;
        for (int i = tid; i < deg; i += 256) {
            int e = sorted[beg + i];
            mx = fmaxf(mx, elog[(size_t)e * H + h]);
        }
#pragma unroll
        for (int o = 16; o > 0; o >>= 1) mx = fmaxf(mx, __shfl_down_sync(0xffffffffu, mx, o));
        if ((tid & 31) == 0) sh[tid >> 5] = mx;
        __syncthreads();
        if (tid < 8) {
            mx = sh[tid];
#pragma unroll
            for (int o = 4; o > 0; o >>= 1) mx = fmaxf(mx, __shfl_down_sync(0xffu, mx, o));
            if (tid == 0) s_bcast = mx;
        }
        __syncthreads();
        float gmax = s_bcast;

        float sm = 0.f;
        for (int i = tid; i < deg; i += 256) {
            int e = sorted[beg + i];
            sm += __expf(elog[(size_t)e * H + h] - gmax);
        }
#pragma unroll
        for (int o = 16; o > 0; o >>= 1) sm += __shfl_down_sync(0xffffffffu, sm, o);
        if ((tid & 31) == 0) sh[tid >> 5] = sm;
        __syncthreads();
        if (tid < 8) {
            sm = sh[tid];
#pragma unroll
            for (int o = 4; o > 0; o >>= 1) sm += __shfl_down_sync(0xffu, sm, o);
            if (tid == 0) s_bcast = sm;
        }
        __syncthreads();
        float inv = 1.f / (s_bcast + 1e-16f);

        float acc = 0.f;
        for (int base = 0; base < deg; base += 256) {
            __syncthreads();
            int i = base + tid;
            if (i < deg) {
                int e = sorted[beg + i];
                s_alpha[tid] = __expf(elog[(size_t)e * H + h] - gmax) * inv;
                s_row[tid]   = src[e];
            }
            __syncthreads();
            int lim = deg - base; if (lim > 256) lim = 256;
            for (int j = 0; j < lim; j++) {
                acc += s_alpha[j] * xp[(size_t)s_row[j] * HC + h * CDIM + tid];
            }
        }
        out[(size_t)d * HC + h * CDIM + tid] = fmaxf(acc + bias[h * CDIM + tid], 0.f);
        __syncthreads();
    }
}

// --------------------------------- host -------------------------------------
static void run_gemm(const float* A, const float* BT, const float* bias, float* C,
                     int M, int N, int K, bool relu) {
    dim3 grid((N + BN - 1) / BN, (M + BM - 1) / BM);
    mma_gemm_kernel<<<grid, 256>>>(M, N, K, A, BT, bias, C, relu ? 1 : 0);
}

// transpose W [R, C] into wT as [C, R], then GEMM with BT = wT
static void run_gemm_w(const float* A, const float* W, int R, int C,
                       const float* bias, float* out, int M, bool relu, float* wT) {
    transpose_kernel<<<dim3((C + 31) / 32, (R + 31) / 32), dim3(32, 8)>>>(W, wT, R, C);
    run_gemm(A, wT, bias, out, M, C, R, relu);
}

static void run_tower(const float* x, int N, int E, const int* src, const int* dst,
                      const float* W1, const float* a1s, const float* a1d, const float* b1,
                      const float* W2, const float* a2s, const float* a2d, const float* b2,
                      const float* lw1, const float* lb1, const float* lw2, const float* lb2,
                      const float* lw3, const float* lb3, float* xfin,
                      float* bufA, float* bufB, float* bufC, float* als, float* ald,
                      float* elog, int* deg, int* off, int* cur, int* sorted, float* wT) {
    // counting-sort edges by destination
    zero_int_kernel<<<(N + 256) / 256, 256>>>(deg, N + 1);
    zero_int_kernel<<<(N + 255) / 256, 256>>>(cur, N);
    hist_kernel<<<(E + 255) / 256, 256>>>(dst, E, deg);
    scan_kernel<<<1, 1024>>>(deg, off, N);
    scatter_kernel<<<(E + 255) / 256, 256>>>(dst, E, off, cur, sorted);

    // GAT layer 1 (H=2, concat -> 512)
    run_gemm_w(x, W1, 256, 512, nullptr, bufA, N, false, wT);
    compute_al<<<N, 256>>>(bufA, a1s, a1d, als, ald, 2);
    edge_logits<<<(E + 255) / 256, 256>>>(src, dst, als, ald, elog, E, 2);
    gat_aggregate<<<N, 256>>>(bufA, elog, src, sorted, off, b1, bufB, 2);

    // GAT layer 2 (H=1 -> 256)
    run_gemm_w(bufB, W2, 512, 256, nullptr, bufA, N, false, wT);
    compute_al<<<N, 256>>>(bufA, a2s, a2d, als, ald, 1);
    edge_logits<<<(E + 255) / 256, 256>>>(src, dst, als, ald, elog, E, 1);
    gat_aggregate<<<N, 256>>>(bufA, elog, src, sorted, off, b2, bufC, 1);

    // MLP head: 256->256->128->64, relu each
    run_gemm_w(bufC, lw1, 256, 256, lb1, bufA, N, true, wT);
    run_gemm_w(bufA, lw2, 256, 128, lb2, bufB, N, true, wT);
    run_gemm_w(bufB, lw3, 128, 64,  lb3, xfin, N, true, wT);
}

extern "C" void kernel_launch(void* const* d_in, const int* in_sizes, int n_in,
                              void* d_out, int out_size) {
    const float* x_m  = (const float*)d_in[0];
    const float* x_d  = (const float*)d_in[1];
    const int*   eix  = (const int*)d_in[2];
    const int*   eiy  = (const int*)d_in[3];
    const float* Wx1 = (const float*)d_in[4];
    const float* ax1s = (const float*)d_in[5];
    const float* ax1d = (const float*)d_in[6];
    const float* bx1 = (const float*)d_in[7];
    const float* Wx2 = (const float*)d_in[8];
    const float* ax2s = (const float*)d_in[9];
    const float* ax2d = (const float*)d_in[10];
    const float* bx2 = (const float*)d_in[11];
    const float* Wy1 = (const float*)d_in[12];
    const float* ay1s = (const float*)d_in[13];
    const float* ay1d = (const float*)d_in[14];
    const float* by1 = (const float*)d_in[15];
    const float* Wy2 = (const float*)d_in[16];
    const float* ay2s = (const float*)d_in[17];
    const float* ay2d = (const float*)d_in[18];
    const float* by2 = (const float*)d_in[19];
    const float* lwx1 = (const float*)d_in[20];
    const float* lbx1 = (const float*)d_in[21];
    const float* lwx2 = (const float*)d_in[22];
    const float* lbx2 = (const float*)d_in[23];
    const float* lwx3 = (const float*)d_in[24];
    const float* lbx3 = (const float*)d_in[25];
    const float* lwy1 = (const float*)d_in[26];
    const float* lby1 = (const float*)d_in[27];
    const float* lwy2 = (const float*)d_in[28];
    const float* lby2 = (const float*)d_in[29];
    const float* lwy3 = (const float*)d_in[30];
    const float* lby3 = (const float*)d_in[31];

    int M  = in_sizes[0] / 256;
    int D  = in_sizes[1] / 256;
    int EX = in_sizes[2] / 2;
    int EY = in_sizes[3] / 2;

    float *bufA, *bufB, *bufC, *als, *ald, *elog, *xfin, *yfin, *wT;
    int *deg, *off, *cur, *sorted;
    cudaGetSymbolAddress((void**)&bufA, g_bufA);
    cudaGetSymbolAddress((void**)&bufB, g_bufB);
    cudaGetSymbolAddress((void**)&bufC, g_bufC);
    cudaGetSymbolAddress((void**)&als, g_als);
    cudaGetSymbolAddress((void**)&ald, g_ald);
    cudaGetSymbolAddress((void**)&elog, g_elog);
    cudaGetSymbolAddress((void**)&deg, g_deg);
    cudaGetSymbolAddress((void**)&off, g_off);
    cudaGetSymbolAddress((void**)&cur, g_cur);
    cudaGetSymbolAddress((void**)&sorted, g_sorted);
    cudaGetSymbolAddress((void**)&xfin, g_xfin);
    cudaGetSymbolAddress((void**)&yfin, g_yfin);
    cudaGetSymbolAddress((void**)&wT, g_wT);

    // X tower
    run_tower(x_m, M, EX, eix, eix + EX,
              Wx1, ax1s, ax1d, bx1, Wx2, ax2s, ax2d, bx2,
              lwx1, lbx1, lwx2, lbx2, lwx3, lbx3, xfin,
              bufA, bufB, bufC, als, ald, elog, deg, off, cur, sorted, wT);
    // Y tower
    run_tower(x_d, D, EY, eiy, eiy + EY,
              Wy1, ay1s, ay1d, by1, Wy2, ay2s, ay2d, by2,
              lwy1, lby1, lwy2, lby2, lwy3, lby3, yfin,
              bufA, bufB, bufC, als, ald, elog, deg, off, cur, sorted, wT);

    // out = xfin @ yfin^T : yfin [D,64] is already the K-major BT operand
    run_gemm(xfin, yfin, nullptr, (float*)d_out, M, D, 64, false);
}

// round 4
// speedup vs baseline: 1.6950x; 1.2265x over previous
#include <cuda_runtime.h>
#include <cuda_bf16.h>
#include <math.h>
#include <stdint.h>

// ----------------------------------------------------------------------------
// Problem constants (this instance): M=D=10000, FG=FD=256, H1=2, K=64, E=320000
// ----------------------------------------------------------------------------
#define MAXN 10000
#define MAXE 320000
#define CDIM 256   // per-head channel dim (FG == FD == 256)

// ------------------------- device scratch (no mallocs) ----------------------
// Tower X set
__device__ float g_bufA[MAXN * 512];
__device__ float g_bufB[MAXN * 512];
__device__ float g_bufC[MAXN * 256];
__device__ float g_als[MAXN * 2];
__device__ float g_ald[MAXN * 2];
__device__ float g_elog[MAXE * 2];
__device__ int   g_deg[MAXN + 1];
__device__ int   g_off[MAXN + 1];
__device__ int   g_cur[MAXN];
__device__ int   g_sorted[MAXE];
__device__ float g_xfin[MAXN * 64];
// Tower Y set (independent for stream overlap)
__device__ float g2_bufA[MAXN * 512];
__device__ float g2_bufB[MAXN * 512];
__device__ float g2_bufC[MAXN * 256];
__device__ float g2_als[MAXN * 2];
__device__ float g2_ald[MAXN * 2];
__device__ float g2_elog[MAXE * 2];
__device__ int   g2_deg[MAXN + 1];
__device__ int   g2_off[MAXN + 1];
__device__ int   g2_cur[MAXN];
__device__ int   g2_sorted[MAXE];
__device__ float g_yfin[MAXN * 64];

// ------------------------------ tiny kernels --------------------------------
__global__ void zero_int_kernel(int* p, int n) {
    int i = blockIdx.x * blockDim.x + threadIdx.x;
    if (i < n) p[i] = 0;
}

__global__ void hist_kernel(const int* __restrict__ dst, int E, int* __restrict__ deg) {
    int e = blockIdx.x * blockDim.x + threadIdx.x;
    if (e < E) atomicAdd(&deg[dst[e]], 1);
}

__global__ void scan_kernel(const int* __restrict__ deg, int* __restrict__ off, int n) {
    const int T = 1024;
    int t = threadIdx.x;
    int chunk = (n + T - 1) / T;
    int b = t * chunk;
    int e2 = b + chunk; if (e2 > n) e2 = n;
    int s = 0;
    for (int i = b; i < e2; i++) s += deg[i];
    __shared__ int sh[T];
    sh[t] = s;
    __syncthreads();
    for (int d2 = 1; d2 < T; d2 <<= 1) {
        int v = (t >= d2) ? sh[t - d2] : 0;
        __syncthreads();
        sh[t] += v;
        __syncthreads();
    }
    int run = (t == 0) ? 0 : sh[t - 1];
    for (int i = b; i < e2; i++) { off[i] = run; run += deg[i]; }
    if (t == 0) off[n] = sh[T - 1];
}

__global__ void scatter_kernel(const int* __restrict__ dst, int E,
                               const int* __restrict__ off, int* __restrict__ cur,
                               int* __restrict__ sorted) {
    int e = blockIdx.x * blockDim.x + threadIdx.x;
    if (e < E) {
        int d = dst[e];
        int p = atomicAdd(&cur[d], 1);
        sorted[off[d] + p] = e;
    }
}

// ------------------------ tf32x3 GEMM via mma.sync --------------------------
// C[M,N] = A[M,K] @ op(B) (+bias, +relu). op(B): bRowMajor=0 -> B is BT [N,K];
// bRowMajor=1 -> B is [K,N] row-major (weights; transpose folded into loader).
// hi/lo tf32 split; 3 mma terms. CTA 128x128, 8 warps of 32x64, BK=16.
#define BM 128
#define BN 128
#define BK 16
#define PADK 20
#define BNP 136   // Bs row stride: 136 mod 32 == 8 -> conflict-free frag LDS

__device__ __forceinline__ float tf32_rn(float a) {
    uint32_t u;
    asm("cvt.rna.tf32.f32 %0, %1;" : "=r"(u) : "f"(a));
    return __uint_as_float(u);
}

__device__ __forceinline__ void mma_m16n8k8(float* c, const uint32_t* a,
                                            const uint32_t* b) {
    asm volatile(
        "mma.sync.aligned.m16n8k8.row.col.f32.tf32.tf32.f32 "
        "{%0,%1,%2,%3}, {%4,%5,%6,%7}, {%8,%9}, {%0,%1,%2,%3};"
        : "+f"(c[0]), "+f"(c[1]), "+f"(c[2]), "+f"(c[3])
        : "r"(a[0]), "r"(a[1]), "r"(a[2]), "r"(a[3]), "r"(b[0]), "r"(b[1]));
}

__global__ __launch_bounds__(256)
void mma_gemm_kernel(int M, int N, int K,
                     const float* __restrict__ A,    // [M, K]
                     const float* __restrict__ B,    // see bRowMajor
                     int bRowMajor,
                     const float* __restrict__ bias, // [N] or null
                     float* __restrict__ C, int doRelu) {
    __shared__ float As_hi[BM][PADK];
    __shared__ float As_lo[BM][PADK];
    __shared__ float Bs_hi[BK][BNP];
    __shared__ float Bs_lo[BK][BNP];

    int tid = threadIdx.x, lane = tid & 31, wid = tid >> 5;
    int mBase = blockIdx.y * BM, nBase = blockIdx.x * BN;
    int wm = (wid & 3) * 32;
    int wn = (wid >> 2) * 64;

    float acc[2][8][4];
#pragma unroll
    for (int i = 0; i < 2; i++)
#pragma unroll
        for (int j = 0; j < 8; j++)
#pragma unroll
            for (int l = 0; l < 4; l++) acc[i][j][l] = 0.f;

    // A loader mapping (512 float4 / chunk; 2 per thread)
    int aRow[2], aKq[2];
#pragma unroll
    for (int it = 0; it < 2; it++) {
        int idx = tid + it * 256;
        aRow[it] = idx >> 2;
        aKq[it] = idx & 3;
    }
    // B loader mapping, row-major path: kk = idx>>5, n4 = (idx&31)*4
    int bKk[2], bN4[2];
#pragma unroll
    for (int it = 0; it < 2; it++) {
        int idx = tid + it * 256;
        bKk[it] = idx >> 5;
        bN4[it] = (idx & 31) * 4;
    }

    int KC = K >> 4;
    float4 pa[2], pb[2];

    auto loadA = [&](int k0) {
#pragma unroll
        for (int it = 0; it < 2; it++) {
            int gm = mBase + aRow[it];
            pa[it] = (gm < M) ? *(const float4*)&A[(size_t)gm * K + k0 + aKq[it] * 4]
                              : make_float4(0.f, 0.f, 0.f, 0.f);
        }
    };
    auto loadB = [&](int k0) {
        if (bRowMajor) {
#pragma unroll
            for (int it = 0; it < 2; it++) {
                int gn = nBase + bN4[it];
                pb[it] = (gn < N) ? *(const float4*)&B[(size_t)(k0 + bKk[it]) * N + gn]
                                  : make_float4(0.f, 0.f, 0.f, 0.f);
            }
        } else {
#pragma unroll
            for (int it = 0; it < 2; it++) {
                int gn = nBase + aRow[it];
                pb[it] = (gn < N) ? *(const float4*)&B[(size_t)gn * K + k0 + aKq[it] * 4]
                                  : make_float4(0.f, 0.f, 0.f, 0.f);
            }
        }
    };
    auto storeA = [&]() {
#pragma unroll
        for (int it = 0; it < 2; it++) {
            float4 v = pa[it], h, l;
            h.x = tf32_rn(v.x); l.x = tf32_rn(v.x - h.x);
            h.y = tf32_rn(v.y); l.y = tf32_rn(v.y - h.y);
            h.z = tf32_rn(v.z); l.z = tf32_rn(v.z - h.z);
            h.w = tf32_rn(v.w); l.w = tf32_rn(v.w - h.w);
            *(float4*)&As_hi[aRow[it]][aKq[it] * 4] = h;
            *(float4*)&As_lo[aRow[it]][aKq[it] * 4] = l;
        }
    };
    auto storeB = [&]() {
        if (bRowMajor) {
#pragma unroll
            for (int it = 0; it < 2; it++) {
                float4 v = pb[it], h, l;
                h.x = tf32_rn(v.x); l.x = tf32_rn(v.x - h.x);
                h.y = tf32_rn(v.y); l.y = tf32_rn(v.y - h.y);
                h.z = tf32_rn(v.z); l.z = tf32_rn(v.z - h.z);
                h.w = tf32_rn(v.w); l.w = tf32_rn(v.w - h.w);
                *(float4*)&Bs_hi[bKk[it]][bN4[it]] = h;
                *(float4*)&Bs_lo[bKk[it]][bN4[it]] = l;
            }
        } else {
#pragma unroll
            for (int it = 0; it < 2; it++) {
                float4 v = pb[it], h, l;
                h.x = tf32_rn(v.x); l.x = tf32_rn(v.x - h.x);
                h.y = tf32_rn(v.y); l.y = tf32_rn(v.y - h.y);
                h.z = tf32_rn(v.z); l.z = tf32_rn(v.z - h.z);
                h.w = tf32_rn(v.w); l.w = tf32_rn(v.w - h.w);
                int n = aRow[it], kq = aKq[it] * 4;
                Bs_hi[kq + 0][n] = h.x; Bs_lo[kq + 0][n] = l.x;
                Bs_hi[kq + 1][n] = h.y; Bs_lo[kq + 1][n] = l.y;
                Bs_hi[kq + 2][n] = h.z; Bs_lo[kq + 2][n] = l.z;
                Bs_hi[kq + 3][n] = h.w; Bs_lo[kq + 3][n] = l.w;
            }
        }
    };

    loadA(0); loadB(0);
    storeA(); storeB();
    __syncthreads();

    for (int ch = 0; ch < KC; ch++) {
        if (ch + 1 < KC) { loadA((ch + 1) << 4); loadB((ch + 1) << 4); }

#pragma unroll
        for (int ks = 0; ks < 2; ks++) {
            int kk = ks * 8 + (lane & 3);
            int ar = wm + (lane >> 2);
            uint32_t ah[2][4], al[2][4];
#pragma unroll
            for (int mt = 0; mt < 2; mt++) {
                int r = ar + mt * 16;
                ah[mt][0] = __float_as_uint(As_hi[r][kk]);
                ah[mt][1] = __float_as_uint(As_hi[r + 8][kk]);
                ah[mt][2] = __float_as_uint(As_hi[r][kk + 4]);
                ah[mt][3] = __float_as_uint(As_hi[r + 8][kk + 4]);
                al[mt][0] = __float_as_uint(As_lo[r][kk]);
                al[mt][1] = __float_as_uint(As_lo[r + 8][kk]);
                al[mt][2] = __float_as_uint(As_lo[r][kk + 4]);
                al[mt][3] = __float_as_uint(As_lo[r + 8][kk + 4]);
            }
            int bk = ks * 8 + (lane & 3);
#pragma unroll
            for (int nt = 0; nt < 8; nt++) {
                int bn = wn + nt * 8 + (lane >> 2);
                uint32_t bh[2], bl[2];
                bh[0] = __float_as_uint(Bs_hi[bk][bn]);
                bh[1] = __float_as_uint(Bs_hi[bk + 4][bn]);
                bl[0] = __float_as_uint(Bs_lo[bk][bn]);
                bl[1] = __float_as_uint(Bs_lo[bk + 4][bn]);
#pragma unroll
                for (int mt = 0; mt < 2; mt++) {
                    mma_m16n8k8(acc[mt][nt], ah[mt], bh);
                    mma_m16n8k8(acc[mt][nt], al[mt], bh);
                    mma_m16n8k8(acc[mt][nt], ah[mt], bl);
                }
            }
        }
        __syncthreads();

        if (ch + 1 < KC) {
            storeA(); storeB();
            __syncthreads();
        }
    }

    // epilogue
#pragma unroll
    for (int mt = 0; mt < 2; mt++) {
        int r0 = mBase + wm + mt * 16 + (lane >> 2);
        int r1 = r0 + 8;
#pragma unroll
        for (int nt = 0; nt < 8; nt++) {
            int c = nBase + wn + nt * 8 + (lane & 3) * 2;
            if (c >= N) continue;
            float b0 = bias ? bias[c] : 0.f;
            float b1 = bias ? bias[c + 1] : 0.f;
            if (r0 < M) {
                float v0 = acc[mt][nt][0] + b0;
                float v1 = acc[mt][nt][1] + b1;
                if (doRelu) { v0 = fmaxf(v0, 0.f); v1 = fmaxf(v1, 0.f); }
                *(float2*)&C[(size_t)r0 * N + c] = make_float2(v0, v1);
            }
            if (r1 < M) {
                float v2 = acc[mt][nt][2] + b0;
                float v3 = acc[mt][nt][3] + b1;
                if (doRelu) { v2 = fmaxf(v2, 0.f); v3 = fmaxf(v3, 0.f); }
                *(float2*)&C[(size_t)r1 * N + c] = make_float2(v2, v3);
            }
        }
    }
}

// --------------------------- GAT-specific kernels ---------------------------
__global__ void compute_al(const float* __restrict__ xp,
                           const float* __restrict__ asrc, const float* __restrict__ adst,
                           float* __restrict__ als, float* __restrict__ ald, int H) {
    int n = blockIdx.x, tid = threadIdx.x;
    int HC = H * CDIM;
    __shared__ float sh1[8], sh2[8];
    for (int h = 0; h < H; h++) {
        float v = xp[(size_t)n * HC + h * CDIM + tid];
        float s1 = v * asrc[h * CDIM + tid];
        float s2 = v * adst[h * CDIM + tid];
#pragma unroll
        for (int o = 16; o > 0; o >>= 1) {
            s1 += __shfl_down_sync(0xffffffffu, s1, o);
            s2 += __shfl_down_sync(0xffffffffu, s2, o);
        }
        if ((tid & 31) == 0) { sh1[tid >> 5] = s1; sh2[tid >> 5] = s2; }
        __syncthreads();
        if (tid < 8) {
            s1 = sh1[tid]; s2 = sh2[tid];
#pragma unroll
            for (int o = 4; o > 0; o >>= 1) {
                s1 += __shfl_down_sync(0xffu, s1, o);
                s2 += __shfl_down_sync(0xffu, s2, o);
            }
            if (tid == 0) { als[n * H + h] = s1; ald[n * H + h] = s2; }
        }
        __syncthreads();
    }
}

__global__ void edge_logits(const int* __restrict__ src, const int* __restrict__ dst,
                            const float* __restrict__ als, const float* __restrict__ ald,
                            float* __restrict__ elog, int E, int H) {
    int e = blockIdx.x * blockDim.x + threadIdx.x;
    if (e >= E) return;
    int s = src[e], d = dst[e];
    for (int h = 0; h < H; h++) {
        float v = als[s * H + h] + ald[d * H + h];
        elog[(size_t)e * H + h] = v > 0.f ? v : 0.2f * v;
    }
}

__global__ void gat_aggregate(const float* __restrict__ xp, const float* __restrict__ elog,
                              const int* __restrict__ src, const int* __restrict__ sorted,
                              const int* __restrict__ off, const float* __restrict__ bias,
                              float* __restrict__ out, int H) {
    int d = blockIdx.x, tid = threadIdx.x;
    int beg = off[d];
    int deg = off[d + 1] - beg;
    int HC = H * CDIM;
    __shared__ float sh[8];
    __shared__ float s_bcast;
    __shared__ float s_alpha[256];
    __shared__ int   s_row[256];

    for (int h = 0; h < H; h++) {
        float mx = -1e30f;
        for (int i = tid; i < deg; i += 256) {
            int e = sorted[beg + i];
            mx = fmaxf(mx, elog[(size_t)e * H + h]);
        }
#pragma unroll
        for (int o = 16; o > 0; o >>= 1) mx = fmaxf(mx, __shfl_down_sync(0xffffffffu, mx, o));
        if ((tid & 31) == 0) sh[tid >> 5] = mx;
        __syncthreads();
        if (tid < 8) {
            mx = sh[tid];
#pragma unroll
            for (int o = 4; o > 0; o >>= 1) mx = fmaxf(mx, __shfl_down_sync(0xffu, mx, o));
            if (tid == 0) s_bcast = mx;
        }
        __syncthreads();
        float gmax = s_bcast;

        float sm = 0.f;
        for (int i = tid; i < deg; i += 256) {
            int e = sorted[beg + i];
            sm += __expf(elog[(size_t)e * H + h] - gmax);
        }
#pragma unroll
        for (int o = 16; o > 0; o >>= 1) sm += __shfl_down_sync(0xffffffffu, sm, o);
        if ((tid & 31) == 0) sh[tid >> 5] = sm;
        __syncthreads();
        if (tid < 8) {
            sm = sh[tid];
#pragma unroll
            for (int o = 4; o > 0; o >>= 1) sm += __shfl_down_sync(0xffu, sm, o);
            if (tid == 0) s_bcast = sm;
        }
        __syncthreads();
        float inv = 1.f / (s_bcast + 1e-16f);

        float acc = 0.f;
        for (int base = 0; base < deg; base += 256) {
            __syncthreads();
            int i = base + tid;
            if (i < deg) {
                int e = sorted[beg + i];
                s_alpha[tid] = __expf(elog[(size_t)e * H + h] - gmax) * inv;
                s_row[tid]   = src[e];
            }
            __syncthreads();
            int lim = deg - base; if (lim > 256) lim = 256;
            for (int j = 0; j < lim; j++) {
                acc += s_alpha[j] * xp[(size_t)s_row[j] * HC + h * CDIM + tid];
            }
        }
        out[(size_t)d * HC + h * CDIM + tid] = fmaxf(acc + bias[h * CDIM + tid], 0.f);
        __syncthreads();
    }
}

// --------------------------------- host -------------------------------------
static void run_gemm(cudaStream_t st, const float* A, const float* B, int bRowMajor,
                     const float* bias, float* C, int M, int N, int K, bool relu) {
    dim3 grid((N + BN - 1) / BN, (M + BM - 1) / BM);
    mma_gemm_kernel<<<grid, 256, 0, st>>>(M, N, K, A, B, bRowMajor, bias, C,
                                          relu ? 1 : 0);
}

static void run_tower(cudaStream_t st,
                      const float* x, int N, int E, const int* src, const int* dst,
                      const float* W1, const float* a1s, const float* a1d, const float* b1,
                      const float* W2, const float* a2s, const float* a2d, const float* b2,
                      const float* lw1, const float* lb1, const float* lw2, const float* lb2,
                      const float* lw3, const float* lb3, float* xfin,
                      float* bufA, float* bufB, float* bufC, float* als, float* ald,
                      float* elog, int* deg, int* off, int* cur, int* sorted) {
    // counting-sort edges by destination (5 launches, then gemm1 is launch #5
    // on the X tower -> lands in ncu's -s 5 -c 1 slot)
    zero_int_kernel<<<(N + 256) / 256, 256, 0, st>>>(deg, N + 1);
    zero_int_kernel<<<(N + 255) / 256, 256, 0, st>>>(cur, N);
    hist_kernel<<<(E + 255) / 256, 256, 0, st>>>(dst, E, deg);
    scan_kernel<<<1, 1024, 0, st>>>(deg, off, N);
    scatter_kernel<<<(E + 255) / 256, 256, 0, st>>>(dst, E, off, cur, sorted);

    // GAT layer 1 (H=2, concat -> 512)
    run_gemm(st, x, W1, 1, nullptr, bufA, N, 512, 256, false);
    compute_al<<<N, 256, 0, st>>>(bufA, a1s, a1d, als, ald, 2);
    edge_logits<<<(E + 255) / 256, 256, 0, st>>>(src, dst, als, ald, elog, E, 2);
    gat_aggregate<<<N, 256, 0, st>>>(bufA, elog, src, sorted, off, b1, bufB, 2);

    // GAT layer 2 (H=1 -> 256)
    run_gemm(st, bufB, W2, 1, nullptr, bufA, N, 256, 512, false);
    compute_al<<<N, 256, 0, st>>>(bufA, a2s, a2d, als, ald, 1);
    edge_logits<<<(E + 255) / 256, 256, 0, st>>>(src, dst, als, ald, elog, E, 1);
    gat_aggregate<<<N, 256, 0, st>>>(bufA, elog, src, sorted, off, b2, bufC, 1);

    // MLP head: 256->256->128->64, relu each
    run_gemm(st, bufC, lw1, 1, lb1, bufA, N, 256, 256, true);
    run_gemm(st, bufA, lw2, 1, lb2, bufB, N, 128, 256, true);
    run_gemm(st, bufB, lw3, 1, lb3, xfin, N, 64, 128, true);
}

extern "C" void kernel_launch(void* const* d_in, const int* in_sizes, int n_in,
                              void* d_out, int out_size) {
    const float* x_m  = (const float*)d_in[0];
    const float* x_d  = (const float*)d_in[1];
    const int*   eix  = (const int*)d_in[2];
    const int*   eiy  = (const int*)d_in[3];
    const float* Wx1 = (const float*)d_in[4];
    const float* ax1s = (const float*)d_in[5];
    const float* ax1d = (const float*)d_in[6];
    const float* bx1 = (const float*)d_in[7];
    const float* Wx2 = (const float*)d_in[8];
    const float* ax2s = (const float*)d_in[9];
    const float* ax2d = (const float*)d_in[10];
    const float* bx2 = (const float*)d_in[11];
    const float* Wy1 = (const float*)d_in[12];
    const float* ay1s = (const float*)d_in[13];
    const float* ay1d = (const float*)d_in[14];
    const float* by1 = (const float*)d_in[15];
    const float* Wy2 = (const float*)d_in[16];
    const float* ay2s = (const float*)d_in[17];
    const float* ay2d = (const float*)d_in[18];
    const float* by2 = (const float*)d_in[19];
    const float* lwx1 = (const float*)d_in[20];
    const float* lbx1 = (const float*)d_in[21];
    const float* lwx2 = (const float*)d_in[22];
    const float* lbx2 = (const float*)d_in[23];
    const float* lwx3 = (const float*)d_in[24];
    const float* lbx3 = (const float*)d_in[25];
    const float* lwy1 = (const float*)d_in[26];
    const float* lby1 = (const float*)d_in[27];
    const float* lwy2 = (const float*)d_in[28];
    const float* lby2 = (const float*)d_in[29];
    const float* lwy3 = (const float*)d_in[30];
    const float* lby3 = (const float*)d_in[31];

    int M  = in_sizes[0] / 256;
    int D  = in_sizes[1] / 256;
    int EX = in_sizes[2] / 2;
    int EY = in_sizes[3] / 2;

    float *bufA, *bufB, *bufC, *als, *ald, *elog, *xfin;
    int *deg, *off, *cur, *sorted;
    float *bufA2, *bufB2, *bufC2, *als2, *ald2, *elog2, *yfin;
    int *deg2, *off2, *cur2, *sorted2;
    cudaGetSymbolAddress((void**)&bufA, g_bufA);
    cudaGetSymbolAddress((void**)&bufB, g_bufB);
    cudaGetSymbolAddress((void**)&bufC, g_bufC);
    cudaGetSymbolAddress((void**)&als, g_als);
    cudaGetSymbolAddress((void**)&ald, g_ald);
    cudaGetSymbolAddress((void**)&elog, g_elog);
    cudaGetSymbolAddress((void**)&deg, g_deg);
    cudaGetSymbolAddress((void**)&off, g_off);
    cudaGetSymbolAddress((void**)&cur, g_cur);
    cudaGetSymbolAddress((void**)&sorted, g_sorted);
    cudaGetSymbolAddress((void**)&xfin, g_xfin);
    cudaGetSymbolAddress((void**)&bufA2, g2_bufA);
    cudaGetSymbolAddress((void**)&bufB2, g2_bufB);
    cudaGetSymbolAddress((void**)&bufC2, g2_bufC);
    cudaGetSymbolAddress((void**)&als2, g2_als);
    cudaGetSymbolAddress((void**)&ald2, g2_ald);
    cudaGetSymbolAddress((void**)&elog2, g2_elog);
    cudaGetSymbolAddress((void**)&deg2, g2_deg);
    cudaGetSymbolAddress((void**)&off2, g2_off);
    cudaGetSymbolAddress((void**)&cur2, g2_cur);
    cudaGetSymbolAddress((void**)&sorted2, g2_sorted);
    cudaGetSymbolAddress((void**)&yfin, g_yfin);

    // Fork a second stream for the independent Y tower (capture-legal pattern).
    cudaStream_t sY;
    cudaStreamCreateWithFlags(&sY, cudaStreamNonBlocking);
    cudaEvent_t evRoot, evY;
    cudaEventCreateWithFlags(&evRoot, cudaEventDisableTiming);
    cudaEventCreateWithFlags(&evY, cudaEventDisableTiming);

    cudaEventRecord(evRoot, 0);
    cudaStreamWaitEvent(sY, evRoot, 0);

    // X tower on the (captured) legacy stream
    run_tower(0, x_m, M, EX, eix, eix + EX,
              Wx1, ax1s, ax1d, bx1, Wx2, ax2s, ax2d, bx2,
              lwx1, lbx1, lwx2, lbx2, lwx3, lbx3, xfin,
              bufA, bufB, bufC, als, ald, elog, deg, off, cur, sorted);
    // Y tower on the forked stream
    run_tower(sY, x_d, D, EY, eiy, eiy + EY,
              Wy1, ay1s, ay1d, by1, Wy2, ay2s, ay2d, by2,
              lwy1, lby1, lwy2, lby2, lwy3, lby3, yfin,
              bufA2, bufB2, bufC2, als2, ald2, elog2, deg2, off2, cur2, sorted2);

    cudaEventRecord(evY, sY);
    cudaStreamWaitEvent(0, evY, 0);

    // out = xfin @ yfin^T : yfin [D,64] is already the K-major BT operand
    run_gemm(0, xfin, yfin, 0, nullptr, (float*)d_out, M, D, 64, false);
}

// round 5
// speedup vs baseline: 1.8944x; 1.1176x over previous
#include <cuda_runtime.h>
#include <cuda_bf16.h>
#include <math.h>
#include <stdint.h>

// ----------------------------------------------------------------------------
// Problem constants (this instance): M=D=10000, FG=FD=256, H1=2, K=64, E=320000
// ----------------------------------------------------------------------------
#define MAXN 10000
#define MAXE 320000
#define CDIM 256   // per-head channel dim (FG == FD == 256)

// ------------------------- device scratch (no mallocs) ----------------------
// Tower X set
__device__ float g_bufA[MAXN * 512];
__device__ float g_bufB[MAXN * 512];
__device__ float g_bufC[MAXN * 256];
__device__ float g_als[MAXN * 2];
__device__ float g_ald[MAXN * 2];
__device__ float g_elog[MAXE * 2];
__device__ int   g_deg[MAXN + 1];
__device__ int   g_off[MAXN + 1];
__device__ int   g_cur[MAXN];
__device__ int   g_sorted[MAXE];
__device__ float g_xfin[MAXN * 64];
// Tower Y set (independent for stream overlap)
__device__ float g2_bufA[MAXN * 512];
__device__ float g2_bufB[MAXN * 512];
__device__ float g2_bufC[MAXN * 256];
__device__ float g2_als[MAXN * 2];
__device__ float g2_ald[MAXN * 2];
__device__ float g2_elog[MAXE * 2];
__device__ int   g2_deg[MAXN + 1];
__device__ int   g2_off[MAXN + 1];
__device__ int   g2_cur[MAXN];
__device__ int   g2_sorted[MAXE];
__device__ float g_yfin[MAXN * 64];

// ------------------------------ tiny kernels --------------------------------
__global__ void zero_int_kernel(int* p, int n) {
    int i = blockIdx.x * blockDim.x + threadIdx.x;
    if (i < n) p[i] = 0;
}

__global__ void hist_kernel(const int* __restrict__ dst, int E, int* __restrict__ deg) {
    int e = blockIdx.x * blockDim.x + threadIdx.x;
    if (e < E) atomicAdd(&deg[dst[e]], 1);
}

__global__ void scan_kernel(const int* __restrict__ deg, int* __restrict__ off, int n) {
    const int T = 1024;
    int t = threadIdx.x;
    int chunk = (n + T - 1) / T;
    int b = t * chunk;
    int e2 = b + chunk; if (e2 > n) e2 = n;
    int s = 0;
    for (int i = b; i < e2; i++) s += deg[i];
    __shared__ int sh[T];
    sh[t] = s;
    __syncthreads();
    for (int d2 = 1; d2 < T; d2 <<= 1) {
        int v = (t >= d2) ? sh[t - d2] : 0;
        __syncthreads();
        sh[t] += v;
        __syncthreads();
    }
    int run = (t == 0) ? 0 : sh[t - 1];
    for (int i = b; i < e2; i++) { off[i] = run; run += deg[i]; }
    if (t == 0) off[n] = sh[T - 1];
}

__global__ void scatter_kernel(const int* __restrict__ dst, int E,
                               const int* __restrict__ off, int* __restrict__ cur,
                               int* __restrict__ sorted) {
    int e = blockIdx.x * blockDim.x + threadIdx.x;
    if (e < E) {
        int d = dst[e];
        int p = atomicAdd(&cur[d], 1);
        sorted[off[d] + p] = e;
    }
}

// ------------------------ tf32x3 GEMM via mma.sync --------------------------
// C[M,N] = A[M,K] @ op(B) (+bias, +relu). bRowMajor=0 -> B is BT [N,K];
// bRowMajor=1 -> B is [K,N] row-major (weights). hi/lo tf32 split, 3 terms,
// issued term-major for MMA ILP. CTA 128x128, 8 warps of 32x64, BK=16.
#define BM 128
#define BN 128
#define BK 16
#define PADK 20
#define BNP 136

__device__ __forceinline__ float tf32_rn(float a) {
    uint32_t u;
    asm("cvt.rna.tf32.f32 %0, %1;" : "=r"(u) : "f"(a));
    return __uint_as_float(u);
}

__device__ __forceinline__ void mma_m16n8k8(float* c, const uint32_t* a,
                                            const uint32_t* b) {
    asm volatile(
        "mma.sync.aligned.m16n8k8.row.col.f32.tf32.tf32.f32 "
        "{%0,%1,%2,%3}, {%4,%5,%6,%7}, {%8,%9}, {%0,%1,%2,%3};"
        : "+f"(c[0]), "+f"(c[1]), "+f"(c[2]), "+f"(c[3])
        : "r"(a[0]), "r"(a[1]), "r"(a[2]), "r"(a[3]), "r"(b[0]), "r"(b[1]));
}

__global__ __launch_bounds__(256)
void mma_gemm_kernel(int M, int N, int K,
                     const float* __restrict__ A,
                     const float* __restrict__ B,
                     int bRowMajor,
                     const float* __restrict__ bias,
                     float* __restrict__ C, int doRelu) {
    __shared__ float As_hi[BM][PADK];
    __shared__ float As_lo[BM][PADK];
    __shared__ float Bs_hi[BK][BNP];
    __shared__ float Bs_lo[BK][BNP];

    int tid = threadIdx.x, lane = tid & 31, wid = tid >> 5;
    int mBase = blockIdx.y * BM, nBase = blockIdx.x * BN;
    int wm = (wid & 3) * 32;
    int wn = (wid >> 2) * 64;

    float acc[2][8][4];
#pragma unroll
    for (int i = 0; i < 2; i++)
#pragma unroll
        for (int j = 0; j < 8; j++)
#pragma unroll
            for (int l = 0; l < 4; l++) acc[i][j][l] = 0.f;

    int aRow[2], aKq[2];
#pragma unroll
    for (int it = 0; it < 2; it++) {
        int idx = tid + it * 256;
        aRow[it] = idx >> 2;
        aKq[it] = idx & 3;
    }
    int bKk[2], bN4[2];
#pragma unroll
    for (int it = 0; it < 2; it++) {
        int idx = tid + it * 256;
        bKk[it] = idx >> 5;
        bN4[it] = (idx & 31) * 4;
    }

    int KC = K >> 4;
    float4 pa[2], pb[2];

    auto loadA = [&](int k0) {
#pragma unroll
        for (int it = 0; it < 2; it++) {
            int gm = mBase + aRow[it];
            pa[it] = (gm < M) ? *(const float4*)&A[(size_t)gm * K + k0 + aKq[it] * 4]
                              : make_float4(0.f, 0.f, 0.f, 0.f);
        }
    };
    auto loadB = [&](int k0) {
        if (bRowMajor) {
#pragma unroll
            for (int it = 0; it < 2; it++) {
                int gn = nBase + bN4[it];
                pb[it] = (gn < N) ? *(const float4*)&B[(size_t)(k0 + bKk[it]) * N + gn]
                                  : make_float4(0.f, 0.f, 0.f, 0.f);
            }
        } else {
#pragma unroll
            for (int it = 0; it < 2; it++) {
                int gn = nBase + aRow[it];
                pb[it] = (gn < N) ? *(const float4*)&B[(size_t)gn * K + k0 + aKq[it] * 4]
                                  : make_float4(0.f, 0.f, 0.f, 0.f);
            }
        }
    };
    auto storeA = [&]() {
#pragma unroll
        for (int it = 0; it < 2; it++) {
            float4 v = pa[it], h, l;
            h.x = tf32_rn(v.x); l.x = tf32_rn(v.x - h.x);
            h.y = tf32_rn(v.y); l.y = tf32_rn(v.y - h.y);
            h.z = tf32_rn(v.z); l.z = tf32_rn(v.z - h.z);
            h.w = tf32_rn(v.w); l.w = tf32_rn(v.w - h.w);
            *(float4*)&As_hi[aRow[it]][aKq[it] * 4] = h;
            *(float4*)&As_lo[aRow[it]][aKq[it] * 4] = l;
        }
    };
    auto storeB = [&]() {
        if (bRowMajor) {
#pragma unroll
            for (int it = 0; it < 2; it++) {
                float4 v = pb[it], h, l;
                h.x = tf32_rn(v.x); l.x = tf32_rn(v.x - h.x);
                h.y = tf32_rn(v.y); l.y = tf32_rn(v.y - h.y);
                h.z = tf32_rn(v.z); l.z = tf32_rn(v.z - h.z);
                h.w = tf32_rn(v.w); l.w = tf32_rn(v.w - h.w);
                *(float4*)&Bs_hi[bKk[it]][bN4[it]] = h;
                *(float4*)&Bs_lo[bKk[it]][bN4[it]] = l;
            }
        } else {
#pragma unroll
            for (int it = 0; it < 2; it++) {
                float4 v = pb[it], h, l;
                h.x = tf32_rn(v.x); l.x = tf32_rn(v.x - h.x);
                h.y = tf32_rn(v.y); l.y = tf32_rn(v.y - h.y);
                h.z = tf32_rn(v.z); l.z = tf32_rn(v.z - h.z);
                h.w = tf32_rn(v.w); l.w = tf32_rn(v.w - h.w);
                int n = aRow[it], kq = aKq[it] * 4;
                Bs_hi[kq + 0][n] = h.x; Bs_lo[kq + 0][n] = l.x;
                Bs_hi[kq + 1][n] = h.y; Bs_lo[kq + 1][n] = l.y;
                Bs_hi[kq + 2][n] = h.z; Bs_lo[kq + 2][n] = l.z;
                Bs_hi[kq + 3][n] = h.w; Bs_lo[kq + 3][n] = l.w;
            }
        }
    };

    loadA(0); loadB(0);
    storeA(); storeB();
    __syncthreads();

    for (int ch = 0; ch < KC; ch++) {
        if (ch + 1 < KC) { loadA((ch + 1) << 4); loadB((ch + 1) << 4); }

#pragma unroll
        for (int ks = 0; ks < 2; ks++) {
            int kk = ks * 8 + (lane & 3);
            int ar = wm + (lane >> 2);
            uint32_t ah[2][4], al[2][4];
#pragma unroll
            for (int mt = 0; mt < 2; mt++) {
                int r = ar + mt * 16;
                ah[mt][0] = __float_as_uint(As_hi[r][kk]);
                ah[mt][1] = __float_as_uint(As_hi[r + 8][kk]);
                ah[mt][2] = __float_as_uint(As_hi[r][kk + 4]);
                ah[mt][3] = __float_as_uint(As_hi[r + 8][kk + 4]);
                al[mt][0] = __float_as_uint(As_lo[r][kk]);
                al[mt][1] = __float_as_uint(As_lo[r + 8][kk]);
                al[mt][2] = __float_as_uint(As_lo[r][kk + 4]);
                al[mt][3] = __float_as_uint(As_lo[r + 8][kk + 4]);
            }
            int bk = ks * 8 + (lane & 3);
            uint32_t bh[8][2], bl[8][2];
#pragma unroll
            for (int nt = 0; nt < 8; nt++) {
                int bn = wn + nt * 8 + (lane >> 2);
                bh[nt][0] = __float_as_uint(Bs_hi[bk][bn]);
                bh[nt][1] = __float_as_uint(Bs_hi[bk + 4][bn]);
                bl[nt][0] = __float_as_uint(Bs_lo[bk][bn]);
                bl[nt][1] = __float_as_uint(Bs_lo[bk + 4][bn]);
            }
            // term-major issue: 16 independent MMAs between acc reuses
#pragma unroll
            for (int nt = 0; nt < 8; nt++)
#pragma unroll
                for (int mt = 0; mt < 2; mt++)
                    mma_m16n8k8(acc[mt][nt], ah[mt], bh[nt]);
#pragma unroll
            for (int nt = 0; nt < 8; nt++)
#pragma unroll
                for (int mt = 0; mt < 2; mt++)
                    mma_m16n8k8(acc[mt][nt], al[mt], bh[nt]);
#pragma unroll
            for (int nt = 0; nt < 8; nt++)
#pragma unroll
                for (int mt = 0; mt < 2; mt++)
                    mma_m16n8k8(acc[mt][nt], ah[mt], bl[nt]);
        }
        __syncthreads();

        if (ch + 1 < KC) {
            storeA(); storeB();
            __syncthreads();
        }
    }

    // epilogue
#pragma unroll
    for (int mt = 0; mt < 2; mt++) {
        int r0 = mBase + wm + mt * 16 + (lane >> 2);
        int r1 = r0 + 8;
#pragma unroll
        for (int nt = 0; nt < 8; nt++) {
            int c = nBase + wn + nt * 8 + (lane & 3) * 2;
            if (c >= N) continue;
            float b0 = bias ? bias[c] : 0.f;
            float b1 = bias ? bias[c + 1] : 0.f;
            if (r0 < M) {
                float v0 = acc[mt][nt][0] + b0;
                float v1 = acc[mt][nt][1] + b1;
                if (doRelu) { v0 = fmaxf(v0, 0.f); v1 = fmaxf(v1, 0.f); }
                *(float2*)&C[(size_t)r0 * N + c] = make_float2(v0, v1);
            }
            if (r1 < M) {
                float v2 = acc[mt][nt][2] + b0;
                float v3 = acc[mt][nt][3] + b1;
                if (doRelu) { v2 = fmaxf(v2, 0.f); v3 = fmaxf(v3, 0.f); }
                *(float2*)&C[(size_t)r1 * N + c] = make_float2(v2, v3);
            }
        }
    }
}

// --------------------------- GAT-specific kernels ---------------------------
__global__ void compute_al(const float* __restrict__ xp,
                           const float* __restrict__ asrc, const float* __restrict__ adst,
                           float* __restrict__ als, float* __restrict__ ald, int H) {
    int n = blockIdx.x, tid = threadIdx.x;
    int HC = H * CDIM;
    __shared__ float sh1[8], sh2[8];
    for (int h = 0; h < H; h++) {
        float v = xp[(size_t)n * HC + h * CDIM + tid];
        float s1 = v * asrc[h * CDIM + tid];
        float s2 = v * adst[h * CDIM + tid];
#pragma unroll
        for (int o = 16; o > 0; o >>= 1) {
            s1 += __shfl_down_sync(0xffffffffu, s1, o);
            s2 += __shfl_down_sync(0xffffffffu, s2, o);
        }
        if ((tid & 31) == 0) { sh1[tid >> 5] = s1; sh2[tid >> 5] = s2; }
        __syncthreads();
        if (tid < 8) {
            s1 = sh1[tid]; s2 = sh2[tid];
#pragma unroll
            for (int o = 4; o > 0; o >>= 1) {
                s1 += __shfl_down_sync(0xffu, s1, o);
                s2 += __shfl_down_sync(0xffu, s2, o);
            }
            if (tid == 0) { als[n * H + h] = s1; ald[n * H + h] = s2; }
        }
        __syncthreads();
    }
}

__global__ void edge_logits(const int* __restrict__ src, const int* __restrict__ dst,
                            const float* __restrict__ als, const float* __restrict__ ald,
                            float* __restrict__ elog, int E, int H) {
    int e = blockIdx.x * blockDim.x + threadIdx.x;
    if (e >= E) return;
    int s = src[e], d = dst[e];
    for (int h = 0; h < H; h++) {
        float v = als[s * H + h] + ald[d * H + h];
        elog[(size_t)e * H + h] = v > 0.f ? v : 0.2f * v;
    }
}

__global__ void gat_aggregate(const float* __restrict__ xp, const float* __restrict__ elog,
                              const int* __restrict__ src, const int* __restrict__ sorted,
                              const int* __restrict__ off, const float* __restrict__ bias,
                              float* __restrict__ out, int H) {
    int d = blockIdx.x, tid = threadIdx.x;
    int beg = off[d];
    int deg = off[d + 1] - beg;
    int HC = H * CDIM;
    __shared__ float sh[8];
    __shared__ float s_bcast;
    __shared__ float s_alpha[256];
    __shared__ int   s_row[256];

    if (deg <= 256) {
        // ---- fast path: exp computed once, normalization folded at the end ----
        // preload src rows once (shared across heads)
        if (tid < deg) s_row[tid] = src[sorted[beg + tid]];
        for (int h = 0; h < H; h++) {
            // segment max
            float mx = -1e30f;
            if (tid < deg) mx = elog[(size_t)sorted[beg + tid] * H + h];
#pragma unroll
            for (int o = 16; o > 0; o >>= 1)
                mx = fmaxf(mx, __shfl_down_sync(0xffffffffu, mx, o));
            if ((tid & 31) == 0) sh[tid >> 5] = mx;
            __syncthreads();
            if (tid < 8) {
                mx = sh[tid];
#pragma unroll
                for (int o = 4; o > 0; o >>= 1)
                    mx = fmaxf(mx, __shfl_down_sync(0xffu, mx, o));
                if (tid == 0) s_bcast = mx;
            }
            __syncthreads();
            float gmax = s_bcast;

            // exp once, stored; block sum
            float ee = 0.f;
            if (tid < deg)
                ee = __expf(elog[(size_t)sorted[beg + tid] * H + h] - gmax);
            s_alpha[tid] = ee;
            float sm = ee;
#pragma unroll
            for (int o = 16; o > 0; o >>= 1) sm += __shfl_down_sync(0xffffffffu, sm, o);
            if ((tid & 31) == 0) sh[tid >> 5] = sm;
            __syncthreads();
            if (tid < 8) {
                sm = sh[tid];
#pragma unroll
                for (int o = 4; o > 0; o >>= 1) sm += __shfl_down_sync(0xffu, sm, o);
                if (tid == 0) s_bcast = sm;
            }
            __syncthreads();
            float inv = 1.f / (s_bcast + 1e-16f);

            // aggregation, 4-way unrolled accumulators to break FFMA chain
            const float* xph = xp + h * CDIM + tid;
            float a0 = 0.f, a1 = 0.f, a2 = 0.f, a3 = 0.f;
            int j = 0;
            for (; j + 4 <= deg; j += 4) {
                a0 += s_alpha[j + 0] * xph[(size_t)s_row[j + 0] * HC];
                a1 += s_alpha[j + 1] * xph[(size_t)s_row[j + 1] * HC];
                a2 += s_alpha[j + 2] * xph[(size_t)s_row[j + 2] * HC];
                a3 += s_alpha[j + 3] * xph[(size_t)s_row[j + 3] * HC];
            }
            for (; j < deg; j++)
                a0 += s_alpha[j] * xph[(size_t)s_row[j] * HC];
            float acc = ((a0 + a1) + (a2 + a3)) * inv;
            out[(size_t)d * HC + h * CDIM + tid] =
                fmaxf(acc + bias[h * CDIM + tid], 0.f);
            __syncthreads();
        }
        return;
    }

    // ---- general path (deg > 256), original logic ----
    for (int h = 0; h < H; h++) {
        float mx = -1e30f;
        for (int i = tid; i < deg; i += 256) {
            int e = sorted[beg + i];
            mx = fmaxf(mx, elog[(size_t)e * H + h]);
        }
#pragma unroll
        for (int o = 16; o > 0; o >>= 1) mx = fmaxf(mx, __shfl_down_sync(0xffffffffu, mx, o));
        if ((tid & 31) == 0) sh[tid >> 5] = mx;
        __syncthreads();
        if (tid < 8) {
            mx = sh[tid];
#pragma unroll
            for (int o = 4; o > 0; o >>= 1) mx = fmaxf(mx, __shfl_down_sync(0xffu, mx, o));
            if (tid == 0) s_bcast = mx;
        }
        __syncthreads();
        float gmax = s_bcast;

        float sm = 0.f;
        for (int i = tid; i < deg; i += 256) {
            int e = sorted[beg + i];
            sm += __expf(elog[(size_t)e * H + h] - gmax);
        }
#pragma unroll
        for (int o = 16; o > 0; o >>= 1) sm += __shfl_down_sync(0xffffffffu, sm, o);
        if ((tid & 31) == 0) sh[tid >> 5] = sm;
        __syncthreads();
        if (tid < 8) {
            sm = sh[tid];
#pragma unroll
            for (int o = 4; o > 0; o >>= 1) sm += __shfl_down_sync(0xffu, sm, o);
            if (tid == 0) s_bcast = sm;
        }
        __syncthreads();
        float inv = 1.f / (s_bcast + 1e-16f);

        float acc = 0.f;
        for (int base = 0; base < deg; base += 256) {
            __syncthreads();
            int i = base + tid;
            if (i < deg) {
                int e = sorted[beg + i];
                s_alpha[tid] = __expf(elog[(size_t)e * H + h] - gmax) * inv;
                s_row[tid]   = src[e];
            }
            __syncthreads();
            int lim = deg - base; if (lim > 256) lim = 256;
            for (int j = 0; j < lim; j++) {
                acc += s_alpha[j] * xp[(size_t)s_row[j] * HC + h * CDIM + tid];
            }
        }
        out[(size_t)d * HC + h * CDIM + tid] = fmaxf(acc + bias[h * CDIM + tid], 0.f);
        __syncthreads();
    }
}

// --------------------------------- host -------------------------------------
static void run_gemm(cudaStream_t st, const float* A, const float* B, int bRowMajor,
                     const float* bias, float* C, int M, int N, int K, bool relu) {
    dim3 grid((N + BN - 1) / BN, (M + BM - 1) / BM);
    mma_gemm_kernel<<<grid, 256, 0, st>>>(M, N, K, A, B, bRowMajor, bias, C,
                                          relu ? 1 : 0);
}

static void run_tower(cudaStream_t st,
                      const float* x, int N, int E, const int* src, const int* dst,
                      const float* W1, const float* a1s, const float* a1d, const float* b1,
                      const float* W2, const float* a2s, const float* a2d, const float* b2,
                      const float* lw1, const float* lb1, const float* lw2, const float* lb2,
                      const float* lw3, const float* lb3, float* xfin,
                      float* bufA, float* bufB, float* bufC, float* als, float* ald,
                      float* elog, int* deg, int* off, int* cur, int* sorted) {
    // gemm1 placed as this tower's launch #3 (ncu capture slot)
    zero_int_kernel<<<(N + 256) / 256, 256, 0, st>>>(deg, N + 1);
    zero_int_kernel<<<(N + 255) / 256, 256, 0, st>>>(cur, N);
    hist_kernel<<<(E + 255) / 256, 256, 0, st>>>(dst, E, deg);
    run_gemm(st, x, W1, 1, nullptr, bufA, N, 512, 256, false);   // launch #3
    scan_kernel<<<1, 1024, 0, st>>>(deg, off, N);
    scatter_kernel<<<(E + 255) / 256, 256, 0, st>>>(dst, E, off, cur, sorted);

    // GAT layer 1 (H=2, concat -> 512)
    compute_al<<<N, 256, 0, st>>>(bufA, a1s, a1d, als, ald, 2);
    edge_logits<<<(E + 255) / 256, 256, 0, st>>>(src, dst, als, ald, elog, E, 2);
    gat_aggregate<<<N, 256, 0, st>>>(bufA, elog, src, sorted, off, b1, bufB, 2);

    // GAT layer 2 (H=1 -> 256)
    run_gemm(st, bufB, W2, 1, nullptr, bufA, N, 256, 512, false);
    compute_al<<<N, 256, 0, st>>>(bufA, a2s, a2d, als, ald, 1);
    edge_logits<<<(E + 255) / 256, 256, 0, st>>>(src, dst, als, ald, elog, E, 1);
    gat_aggregate<<<N, 256, 0, st>>>(bufA, elog, src, sorted, off, b2, bufC, 1);

    // MLP head: 256->256->128->64, relu each
    run_gemm(st, bufC, lw1, 1, lb1, bufA, N, 256, 256, true);
    run_gemm(st, bufA, lw2, 1, lb2, bufB, N, 128, 256, true);
    run_gemm(st, bufB, lw3, 1, lb3, xfin, N, 64, 128, true);
}

extern "C" void kernel_launch(void* const* d_in, const int* in_sizes, int n_in,
                              void* d_out, int out_size) {
    const float* x_m  = (const float*)d_in[0];
    const float* x_d  = (const float*)d_in[1];
    const int*   eix  = (const int*)d_in[2];
    const int*   eiy  = (const int*)d_in[3];
    const float* Wx1 = (const float*)d_in[4];
    const float* ax1s = (const float*)d_in[5];
    const float* ax1d = (const float*)d_in[6];
    const float* bx1 = (const float*)d_in[7];
    const float* Wx2 = (const float*)d_in[8];
    const float* ax2s = (const float*)d_in[9];
    const float* ax2d = (const float*)d_in[10];
    const float* bx2 = (const float*)d_in[11];
    const float* Wy1 = (const float*)d_in[12];
    const float* ay1s = (const float*)d_in[13];
    const float* ay1d = (const float*)d_in[14];
    const float* by1 = (const float*)d_in[15];
    const float* Wy2 = (const float*)d_in[16];
    const float* ay2s = (const float*)d_in[17];
    const float* ay2d = (const float*)d_in[18];
    const float* by2 = (const float*)d_in[19];
    const float* lwx1 = (const float*)d_in[20];
    const float* lbx1 = (const float*)d_in[21];
    const float* lwx2 = (const float*)d_in[22];
    const float* lbx2 = (const float*)d_in[23];
    const float* lwx3 = (const float*)d_in[24];
    const float* lbx3 = (const float*)d_in[25];
    const float* lwy1 = (const float*)d_in[26];
    const float* lby1 = (const float*)d_in[27];
    const float* lwy2 = (const float*)d_in[28];
    const float* lby2 = (const float*)d_in[29];
    const float* lwy3 = (const float*)d_in[30];
    const float* lby3 = (const float*)d_in[31];

    int M  = in_sizes[0] / 256;
    int D  = in_sizes[1] / 256;
    int EX = in_sizes[2] / 2;
    int EY = in_sizes[3] / 2;

    float *bufA, *bufB, *bufC, *als, *ald, *elog, *xfin;
    int *deg, *off, *cur, *sorted;
    float *bufA2, *bufB2, *bufC2, *als2, *ald2, *elog2, *yfin;
    int *deg2, *off2, *cur2, *sorted2;
    cudaGetSymbolAddress((void**)&bufA, g_bufA);
    cudaGetSymbolAddress((void**)&bufB, g_bufB);
    cudaGetSymbolAddress((void**)&bufC, g_bufC);
    cudaGetSymbolAddress((void**)&als, g_als);
    cudaGetSymbolAddress((void**)&ald, g_ald);
    cudaGetSymbolAddress((void**)&elog, g_elog);
    cudaGetSymbolAddress((void**)&deg, g_deg);
    cudaGetSymbolAddress((void**)&off, g_off);
    cudaGetSymbolAddress((void**)&cur, g_cur);
    cudaGetSymbolAddress((void**)&sorted, g_sorted);
    cudaGetSymbolAddress((void**)&xfin, g_xfin);
    cudaGetSymbolAddress((void**)&bufA2, g2_bufA);
    cudaGetSymbolAddress((void**)&bufB2, g2_bufB);
    cudaGetSymbolAddress((void**)&bufC2, g2_bufC);
    cudaGetSymbolAddress((void**)&als2, g2_als);
    cudaGetSymbolAddress((void**)&ald2, g2_ald);
    cudaGetSymbolAddress((void**)&elog2, g2_elog);
    cudaGetSymbolAddress((void**)&deg2, g2_deg);
    cudaGetSymbolAddress((void**)&off2, g2_off);
    cudaGetSymbolAddress((void**)&cur2, g2_cur);
    cudaGetSymbolAddress((void**)&sorted2, g2_sorted);
    cudaGetSymbolAddress((void**)&yfin, g_yfin);

    cudaStream_t sY;
    cudaStreamCreateWithFlags(&sY, cudaStreamNonBlocking);
    cudaEvent_t evRoot, evY;
    cudaEventCreateWithFlags(&evRoot, cudaEventDisableTiming);
    cudaEventCreateWithFlags(&evY, cudaEventDisableTiming);

    cudaEventRecord(evRoot, 0);
    cudaStreamWaitEvent(sY, evRoot, 0);

    run_tower(0, x_m, M, EX, eix, eix + EX,
              Wx1, ax1s, ax1d, bx1, Wx2, ax2s, ax2d, bx2,
              lwx1, lbx1, lwx2, lbx2, lwx3, lbx3, xfin,
              bufA, bufB, bufC, als, ald, elog, deg, off, cur, sorted);
    run_tower(sY, x_d, D, EY, eiy, eiy + EY,
              Wy1, ay1s, ay1d, by1, Wy2, ay2s, ay2d, by2,
              lwy1, lby1, lwy2, lby2, lwy3, lby3, yfin,
              bufA2, bufB2, bufC2, als2, ald2, elog2, deg2, off2, cur2, sorted2);

    cudaEventRecord(evY, sY);
    cudaStreamWaitEvent(0, evY, 0);

    run_gemm(0, xfin, yfin, 0, nullptr, (float*)d_out, M, D, 64, false);
}